// round 1
// baseline (speedup 1.0000x reference)
#include <cuda_runtime.h>
#include <cstdint>

#define N_NODES 50000
#define N_EDGES 600000
#define IN_DIM  64
#define HIDDEN  128
#define N_REL   10
#define N_LAYERS 6
#define N_GRAPHS 64
#define LN_EPS  1e-5f

#define RK      (N_REL * HIDDEN)      // 1280: agg part of K
#define KTOT    (HIDDEN + RK)         // 1408: full K for layer GEMM
#define BM      64
#define BK      16

// ---------------- device scratch (static, allocation-free) ----------------
__device__ float g_A[(size_t)N_NODES * RK];        // per-(node,rel) aggregated means, 256 MB
__device__ float g_h[2][(size_t)N_NODES * HIDDEN]; // ping-pong node features, 51.2 MB
__device__ int   g_cnt[N_NODES * N_REL];           // per-(node,rel) in-degree

// ---------------- small utility kernels ----------------
__global__ void zero_cnt_kernel() {
    int i = blockIdx.x * blockDim.x + threadIdx.x;
    if (i < N_NODES * N_REL) g_cnt[i] = 0;
}

__global__ void count_kernel(const int* __restrict__ ei, const int* __restrict__ et) {
    int e = blockIdx.x * blockDim.x + threadIdx.x;
    if (e >= N_EDGES) return;
    int dst = ei[N_EDGES + e];
    int r = et[e];
    atomicAdd(&g_cnt[dst * N_REL + r], 1);
}

__global__ void zeroA_kernel() {
    size_t i = (size_t)blockIdx.x * blockDim.x + threadIdx.x; // float4 index
    if (i < (size_t)N_NODES * RK / 4) {
        ((float4*)g_A)[i] = make_float4(0.f, 0.f, 0.f, 0.f);
    }
}

// ---------------- edge scatter: g_A[dst][r][:] += h[src][:] / cnt ----------------
__global__ void scatter_kernel(const int* __restrict__ ei, const int* __restrict__ et, int cur) {
    int e = blockIdx.x * (blockDim.x >> 5) + (threadIdx.x >> 5);
    if (e >= N_EDGES) return;
    int lane = threadIdx.x & 31;
    int src = ei[e];
    int dst = ei[N_EDGES + e];
    int r   = et[e];
    int c   = g_cnt[dst * N_REL + r];      // >= 1 (this edge counted)
    float inv = 1.0f / (float)c;
    const float* hsrc = &g_h[cur][(size_t)src * HIDDEN];
    float4 v = *(const float4*)&hsrc[lane * 4];
    v.x *= inv; v.y *= inv; v.z *= inv; v.w *= inv;
    float* p = &g_A[(size_t)dst * RK + r * HIDDEN + lane * 4];
    asm volatile("red.global.add.v4.f32 [%0], {%1,%2,%3,%4};"
                 :: "l"(p), "f"(v.x), "f"(v.y), "f"(v.z), "f"(v.w) : "memory");
}

// ---------------- input projection: h0 = x @ Wp + bp ----------------
__global__ void proj_kernel(const float* __restrict__ x, const float* __restrict__ Wp,
                            const float* __restrict__ bp) {
    __shared__ float As[BK][BM + 4];
    __shared__ float Bs[BK][HIDDEN];
    int tid = threadIdx.x;           // 256
    int tm = tid >> 5;               // warp id 0..7, 8 rows each
    int tn = tid & 31;               // lane, 4 cols each
    int row0 = blockIdx.x * BM;
    float acc[8][4];
    #pragma unroll
    for (int i = 0; i < 8; i++)
        #pragma unroll
        for (int j = 0; j < 4; j++) acc[i][j] = 0.f;

    for (int k0 = 0; k0 < IN_DIM; k0 += BK) {
        {
            int r = tid >> 2;
            int kc = (tid & 3) * 4;
            int grow = row0 + r;
            float4 v = make_float4(0.f, 0.f, 0.f, 0.f);
            if (grow < N_NODES) v = *(const float4*)&x[(size_t)grow * IN_DIM + k0 + kc];
            As[kc + 0][r] = v.x; As[kc + 1][r] = v.y; As[kc + 2][r] = v.z; As[kc + 3][r] = v.w;
        }
        {
            #pragma unroll
            for (int i = 0; i < 2; i++) {
                int f = tid + i * 256;              // 0..511 float4s of 16x128
                int kk = f >> 5; int c4 = (f & 31) * 4;
                *(float4*)&Bs[kk][c4] = *(const float4*)&Wp[(size_t)(k0 + kk) * HIDDEN + c4];
            }
        }
        __syncthreads();
        #pragma unroll
        for (int kk = 0; kk < BK; kk++) {
            float a[8], b[4];
            *(float4*)&a[0] = *(const float4*)&As[kk][tm * 8];
            *(float4*)&a[4] = *(const float4*)&As[kk][tm * 8 + 4];
            *(float4*)&b[0] = *(const float4*)&Bs[kk][tn * 4];
            #pragma unroll
            for (int i = 0; i < 8; i++)
                #pragma unroll
                for (int j = 0; j < 4; j++) acc[i][j] = fmaf(a[i], b[j], acc[i][j]);
        }
        __syncthreads();
    }
    int n0 = tn * 4;
    float4 bb = *(const float4*)&bp[n0];
    #pragma unroll
    for (int i = 0; i < 8; i++) {
        int grow = row0 + tm * 8 + i;
        if (grow < N_NODES) {
            float4 o = make_float4(acc[i][0] + bb.x, acc[i][1] + bb.y,
                                   acc[i][2] + bb.z, acc[i][3] + bb.w);
            *(float4*)&g_h[0][(size_t)grow * HIDDEN + n0] = o;
        }
    }
}

// ---------------- fused layer GEMM + bias + LayerNorm + ReLU + residual ----------------
// C = [h | agg] @ [root_w ; rel_w] ; then LN, ReLU, + h  -> h_next
__global__ void gemm_ln_kernel(const float* __restrict__ rel_w, const float* __restrict__ root_w,
                               const float* __restrict__ conv_b, const float* __restrict__ ln_g,
                               const float* __restrict__ ln_b, int l, int cur) {
    __shared__ float As[BK][BM + 4];
    __shared__ float Bs[BK][HIDDEN];
    int tid = threadIdx.x;           // 256
    int tm = tid >> 5;               // warp id: 8 rows
    int tn = tid & 31;               // lane: 4 cols
    int row0 = blockIdx.x * BM;
    float acc[8][4];
    #pragma unroll
    for (int i = 0; i < 8; i++)
        #pragma unroll
        for (int j = 0; j < 4; j++) acc[i][j] = 0.f;

    const float* hcur  = g_h[cur];
    const float* Broot = root_w + (size_t)l * HIDDEN * HIDDEN;
    const float* Brel  = rel_w  + (size_t)l * N_REL * HIDDEN * HIDDEN;

    for (int k0 = 0; k0 < KTOT; k0 += BK) {
        // A tile (64 x 16) from h (k<128) or g_A (k>=128), stored transposed
        {
            int r = tid >> 2;
            int kc = (tid & 3) * 4;
            int grow = row0 + r;
            float4 v = make_float4(0.f, 0.f, 0.f, 0.f);
            if (grow < N_NODES) {
                if (k0 < HIDDEN)
                    v = *(const float4*)&hcur[(size_t)grow * HIDDEN + k0 + kc];
                else
                    v = *(const float4*)&g_A[(size_t)grow * RK + (k0 - HIDDEN) + kc];
            }
            As[kc + 0][r] = v.x; As[kc + 1][r] = v.y; As[kc + 2][r] = v.z; As[kc + 3][r] = v.w;
        }
        // B tile (16 x 128)
        {
            const float* Bsrc = (k0 < HIDDEN) ? (Broot + (size_t)k0 * HIDDEN)
                                              : (Brel + (size_t)(k0 - HIDDEN) * HIDDEN);
            #pragma unroll
            for (int i = 0; i < 2; i++) {
                int f = tid + i * 256;
                int kk = f >> 5; int c4 = (f & 31) * 4;
                *(float4*)&Bs[kk][c4] = *(const float4*)&Bsrc[(size_t)kk * HIDDEN + c4];
            }
        }
        __syncthreads();
        #pragma unroll
        for (int kk = 0; kk < BK; kk++) {
            float a[8], b[4];
            *(float4*)&a[0] = *(const float4*)&As[kk][tm * 8];
            *(float4*)&a[4] = *(const float4*)&As[kk][tm * 8 + 4];
            *(float4*)&b[0] = *(const float4*)&Bs[kk][tn * 4];
            #pragma unroll
            for (int i = 0; i < 8; i++)
                #pragma unroll
                for (int j = 0; j < 4; j++) acc[i][j] = fmaf(a[i], b[j], acc[i][j]);
        }
        __syncthreads();
    }

    // epilogue: +conv_b, LayerNorm over 128 cols (warp owns a row), ReLU, +residual
    int n0 = tn * 4;
    float4 cb = *(const float4*)&conv_b[l * HIDDEN + n0];
    float4 g4 = *(const float4*)&ln_g[l * HIDDEN + n0];
    float4 b4 = *(const float4*)&ln_b[l * HIDDEN + n0];
    float* hnext = g_h[cur ^ 1];
    #pragma unroll
    for (int i = 0; i < 8; i++) {
        int grow = row0 + tm * 8 + i;
        float v0 = acc[i][0] + cb.x;
        float v1 = acc[i][1] + cb.y;
        float v2 = acc[i][2] + cb.z;
        float v3 = acc[i][3] + cb.w;
        float s  = v0 + v1 + v2 + v3;
        float sq = v0 * v0 + v1 * v1 + v2 * v2 + v3 * v3;
        #pragma unroll
        for (int o = 16; o > 0; o >>= 1) {
            s  += __shfl_xor_sync(0xFFFFFFFFu, s,  o);
            sq += __shfl_xor_sync(0xFFFFFFFFu, sq, o);
        }
        float mu  = s * (1.0f / HIDDEN);
        float var = sq * (1.0f / HIDDEN) - mu * mu;
        float rs  = rsqrtf(var + LN_EPS);
        if (grow < N_NODES) {
            float4 res = *(const float4*)&hcur[(size_t)grow * HIDDEN + n0];
            float4 o;
            o.x = fmaxf((v0 - mu) * rs * g4.x + b4.x, 0.f) + res.x;
            o.y = fmaxf((v1 - mu) * rs * g4.y + b4.y, 0.f) + res.y;
            o.z = fmaxf((v2 - mu) * rs * g4.z + b4.z, 0.f) + res.z;
            o.w = fmaxf((v3 - mu) * rs * g4.w + b4.w, 0.f) + res.w;
            *(float4*)&hnext[(size_t)grow * HIDDEN + n0] = o;
        }
    }
}

// ---------------- pooling: out[g] = sum over nodes with batch[i]==g (batch sorted) ----------------
__device__ __forceinline__ int lower_bound_dev(const int* __restrict__ a, int n, int v) {
    int lo = 0, hi = n;
    while (lo < hi) { int mid = (lo + hi) >> 1; if (a[mid] < v) lo = mid + 1; else hi = mid; }
    return lo;
}

__global__ void pool_kernel(const int* __restrict__ batch, float* __restrict__ out, int finalbuf) {
    int g = blockIdx.x;          // 64
    int tid = threadIdx.x;       // 128 (one col per thread)
    int start = lower_bound_dev(batch, N_NODES, g);
    int end   = lower_bound_dev(batch, N_NODES, g + 1);
    const float* h = g_h[finalbuf];
    float acc = 0.f;
    for (int i = start; i < end; i++)
        acc += h[(size_t)i * HIDDEN + tid];
    out[g * HIDDEN + tid] = acc;
}

// ---------------- launch ----------------
extern "C" void kernel_launch(void* const* d_in, const int* in_sizes, int n_in,
                              void* d_out, int out_size) {
    const float* x      = (const float*)d_in[0];
    const int* ei       = (const int*)d_in[1];
    const int* et       = (const int*)d_in[2];
    const int* batch    = (const int*)d_in[3];
    const float* Wp     = (const float*)d_in[4];
    const float* bp     = (const float*)d_in[5];
    const float* rel_w  = (const float*)d_in[6];
    const float* root_w = (const float*)d_in[7];
    const float* conv_b = (const float*)d_in[8];
    const float* ln_g   = (const float*)d_in[9];
    const float* ln_b   = (const float*)d_in[10];
    float* out = (float*)d_out;

    // degree counts (structure only; once per call)
    zero_cnt_kernel<<<(N_NODES * N_REL + 255) / 256, 256>>>();
    count_kernel<<<(N_EDGES + 255) / 256, 256>>>(ei, et);

    // input projection -> g_h[0]
    proj_kernel<<<(N_NODES + BM - 1) / BM, 256>>>(x, Wp, bp);

    for (int l = 0; l < N_LAYERS; l++) {
        int cur = l & 1;
        zeroA_kernel<<<((N_NODES * (size_t)RK / 4) + 255) / 256, 256>>>();
        scatter_kernel<<<(N_EDGES + 7) / 8, 256>>>(ei, et, cur);
        gemm_ln_kernel<<<(N_NODES + BM - 1) / BM, 256>>>(rel_w, root_w, conv_b, ln_g, ln_b, l, cur);
    }

    // after 6 layers the result is back in g_h[0]
    pool_kernel<<<N_GRAPHS, HIDDEN>>>(batch, out, 0);
}

// round 5
// speedup vs baseline: 1.6696x; 1.6696x over previous
#include <cuda_runtime.h>
#include <cstdint>

#define N_NODES 50000
#define N_EDGES 600000
#define IN_DIM  64
#define HIDDEN  128
#define N_REL   10
#define N_LAYERS 6
#define N_GRAPHS 64
#define LN_EPS  1e-5f

#define RK      (N_REL * HIDDEN)      // 1280
#define KTOT    (HIDDEN + RK)         // 1408
#define NCHUNK  (KTOT / 32)           // 44

// ---------------- device scratch ----------------
__device__ float g_A[(size_t)N_NODES * RK];        // per-(node,rel) means, 256 MB
__device__ float g_h[2][(size_t)N_NODES * HIDDEN]; // ping-pong features
__device__ float g_tmp[(size_t)N_NODES * HIDDEN];  // GEMM output before LN
__device__ int   g_cnt[N_NODES * N_REL];
__device__ float g_Bw[(size_t)KTOT * HIDDEN];      // packed W (tf32 bits) [K][N]

__device__ __forceinline__ float f2tf32(float f) {
    uint32_t r;
    asm("cvt.rna.tf32.f32 %0, %1;" : "=r"(r) : "f"(f));
    return __uint_as_float(r);
}

__device__ __forceinline__ void mma_tf32(float* c, const uint32_t* a, const uint32_t* b) {
    asm volatile(
        "mma.sync.aligned.m16n8k8.row.col.f32.tf32.tf32.f32 "
        "{%0,%1,%2,%3}, {%4,%5,%6,%7}, {%8,%9}, {%0,%1,%2,%3};"
        : "+f"(c[0]), "+f"(c[1]), "+f"(c[2]), "+f"(c[3])
        : "r"(a[0]), "r"(a[1]), "r"(a[2]), "r"(a[3]), "r"(b[0]), "r"(b[1]));
}

// ---------------- small utility kernels ----------------
__global__ void zero_cnt_kernel() {
    int i = blockIdx.x * blockDim.x + threadIdx.x;
    if (i < N_NODES * N_REL) g_cnt[i] = 0;
}

__global__ void count_kernel(const int* __restrict__ ei, const int* __restrict__ et) {
    int e = blockIdx.x * blockDim.x + threadIdx.x;
    if (e >= N_EDGES) return;
    atomicAdd(&g_cnt[ei[N_EDGES + e] * N_REL + et[e]], 1);
}

__global__ void zeroA_kernel() {
    size_t i = (size_t)blockIdx.x * blockDim.x + threadIdx.x;
    if (i < (size_t)N_NODES * RK / 4)
        ((float4*)g_A)[i] = make_float4(0.f, 0.f, 0.f, 0.f);
}

// pack weights for layer l: g_Bw[k][n] = W_full[k][n] (tf32-rounded)
__global__ void bw_kernel(const float* __restrict__ rel_w, const float* __restrict__ root_w, int l) {
    int idx = blockIdx.x * blockDim.x + threadIdx.x;
    if (idx >= KTOT * HIDDEN) return;
    int k = idx / HIDDEN, n = idx % HIDDEN;
    float v;
    if (k < HIDDEN)
        v = root_w[(size_t)l * HIDDEN * HIDDEN + (size_t)k * HIDDEN + n];
    else
        v = rel_w[(size_t)l * N_REL * HIDDEN * HIDDEN + (size_t)(k - HIDDEN) * HIDDEN + n];
    g_Bw[idx] = f2tf32(v);
}

// ---------------- edge scatter ----------------
__global__ void scatter_kernel(const int* __restrict__ ei, const int* __restrict__ et, int cur) {
    int e = blockIdx.x * (blockDim.x >> 5) + (threadIdx.x >> 5);
    if (e >= N_EDGES) return;
    int lane = threadIdx.x & 31;
    int src = ei[e];
    int dst = ei[N_EDGES + e];
    int r   = et[e];
    float inv = 1.0f / (float)g_cnt[dst * N_REL + r];
    float4 v = *(const float4*)&g_h[cur][(size_t)src * HIDDEN + lane * 4];
    v.x *= inv; v.y *= inv; v.z *= inv; v.w *= inv;
    float* p = &g_A[(size_t)dst * RK + r * HIDDEN + lane * 4];
    asm volatile("red.global.add.v4.f32 [%0], {%1,%2,%3,%4};"
                 :: "l"(p), "f"(v.x), "f"(v.y), "f"(v.z), "f"(v.w) : "memory");
}

// ---------------- input projection ----------------
#define BM 64
#define BK 16
__global__ void proj_kernel(const float* __restrict__ x, const float* __restrict__ Wp,
                            const float* __restrict__ bp) {
    __shared__ float As[BK][BM + 4];
    __shared__ float Bs[BK][HIDDEN];
    int tid = threadIdx.x;
    int tm = tid >> 5, tn = tid & 31;
    int row0 = blockIdx.x * BM;
    float acc[8][4];
    #pragma unroll
    for (int i = 0; i < 8; i++)
        #pragma unroll
        for (int j = 0; j < 4; j++) acc[i][j] = 0.f;

    for (int k0 = 0; k0 < IN_DIM; k0 += BK) {
        {
            int r = tid >> 2, kc = (tid & 3) * 4, grow = row0 + r;
            float4 v = make_float4(0.f, 0.f, 0.f, 0.f);
            if (grow < N_NODES) v = *(const float4*)&x[(size_t)grow * IN_DIM + k0 + kc];
            As[kc + 0][r] = v.x; As[kc + 1][r] = v.y; As[kc + 2][r] = v.z; As[kc + 3][r] = v.w;
        }
        #pragma unroll
        for (int i = 0; i < 2; i++) {
            int f = tid + i * 256;
            int kk = f >> 5, c4 = (f & 31) * 4;
            *(float4*)&Bs[kk][c4] = *(const float4*)&Wp[(size_t)(k0 + kk) * HIDDEN + c4];
        }
        __syncthreads();
        #pragma unroll
        for (int kk = 0; kk < BK; kk++) {
            float a[8], b[4];
            *(float4*)&a[0] = *(const float4*)&As[kk][tm * 8];
            *(float4*)&a[4] = *(const float4*)&As[kk][tm * 8 + 4];
            *(float4*)&b[0] = *(const float4*)&Bs[kk][tn * 4];
            #pragma unroll
            for (int i = 0; i < 8; i++)
                #pragma unroll
                for (int j = 0; j < 4; j++) acc[i][j] = fmaf(a[i], b[j], acc[i][j]);
        }
        __syncthreads();
    }
    int n0 = tn * 4;
    float4 bb = *(const float4*)&bp[n0];
    #pragma unroll
    for (int i = 0; i < 8; i++) {
        int grow = row0 + tm * 8 + i;
        if (grow < N_NODES) {
            float4 o = make_float4(acc[i][0] + bb.x, acc[i][1] + bb.y,
                                   acc[i][2] + bb.z, acc[i][3] + bb.w);
            *(float4*)&g_h[0][(size_t)grow * HIDDEN + n0] = o;
        }
    }
}

// ---------------- tf32 mma.sync GEMM: g_tmp = [h | agg] @ W ----------------
// CTA: 128(M) x 128(N), BK=32. 8 warps = 4(M) x 2(N); warp tile 32 x 64.
#define APITCH 36
#define BPITCH 136

__global__ void __launch_bounds__(256, 2)
gemm_mma_kernel(int cur) {
    __shared__ float As[128 * APITCH];   // [m][k], tf32 bits, padded
    __shared__ float Bs[32 * BPITCH];    // [k][n], tf32 bits, padded

    int tid = threadIdx.x;
    int wid = tid >> 5;
    int lane = tid & 31;
    int gq = lane >> 2;                  // groupID 0..7
    int tq = lane & 3;                   // thread-in-group 0..3
    int wm = (wid >> 1) * 32;            // warp M offset
    int wn = (wid & 1) * 64;             // warp N offset
    int row0 = blockIdx.x * 128;
    const float* hcur = g_h[cur];

    float c[2][8][4];
    #pragma unroll
    for (int mi = 0; mi < 2; mi++)
        #pragma unroll
        for (int nj = 0; nj < 8; nj++)
            #pragma unroll
            for (int q = 0; q < 4; q++) c[mi][nj][q] = 0.f;

    const uint32_t* AsU = (const uint32_t*)As;
    const uint32_t* BsU = (const uint32_t*)Bs;

    for (int i = 0; i < NCHUNK; i++) {
        int k0 = i * 32;
        const float* Asrc;
        int stride;
        if (k0 < HIDDEN) { Asrc = hcur + k0; stride = HIDDEN; }
        else             { Asrc = g_A + (k0 - HIDDEN); stride = RK; }

        // global loads (regs)
        float4 av[4], bv[4];
        #pragma unroll
        for (int t = 0; t < 4; t++) {
            int idx = tid + t * 256;            // 0..1023
            int r = idx >> 3, cc = idx & 7;
            int grow = row0 + r;
            av[t] = (grow < N_NODES) ? *(const float4*)&Asrc[(size_t)grow * stride + cc * 4]
                                     : make_float4(0.f, 0.f, 0.f, 0.f);
        }
        #pragma unroll
        for (int t = 0; t < 4; t++) {
            int idx = tid + t * 256;            // 0..1023 over 32x32 float4s
            int kk = idx >> 5, n4 = idx & 31;
            bv[t] = *(const float4*)&g_Bw[(size_t)(k0 + kk) * HIDDEN + n4 * 4];
        }
        __syncthreads();   // previous compute done, smem free
        #pragma unroll
        for (int t = 0; t < 4; t++) {
            int idx = tid + t * 256;
            int r = idx >> 3, cc = idx & 7;
            float4 cv = make_float4(f2tf32(av[t].x), f2tf32(av[t].y),
                                    f2tf32(av[t].z), f2tf32(av[t].w));
            *(float4*)&As[r * APITCH + cc * 4] = cv;
        }
        #pragma unroll
        for (int t = 0; t < 4; t++) {
            int idx = tid + t * 256;
            int kk = idx >> 5, n4 = idx & 31;
            *(float4*)&Bs[kk * BPITCH + n4 * 4] = bv[t];
        }
        __syncthreads();

        // compute
        #pragma unroll
        for (int s = 0; s < 4; s++) {
            int kb = s * 8;
            uint32_t a[2][4], b[8][2];
            #pragma unroll
            for (int mi = 0; mi < 2; mi++) {
                int r = wm + mi * 16 + gq;
                a[mi][0] = AsU[r * APITCH + kb + tq];
                a[mi][1] = AsU[(r + 8) * APITCH + kb + tq];
                a[mi][2] = AsU[r * APITCH + kb + tq + 4];
                a[mi][3] = AsU[(r + 8) * APITCH + kb + tq + 4];
            }
            #pragma unroll
            for (int nj = 0; nj < 8; nj++) {
                int n = wn + nj * 8 + gq;
                b[nj][0] = BsU[(kb + tq) * BPITCH + n];
                b[nj][1] = BsU[(kb + tq + 4) * BPITCH + n];
            }
            #pragma unroll
            for (int mi = 0; mi < 2; mi++)
                #pragma unroll
                for (int nj = 0; nj < 8; nj++)
                    mma_tf32(c[mi][nj], a[mi], b[nj]);
        }
        __syncthreads();
    }

    // store C to g_tmp
    #pragma unroll
    for (int mi = 0; mi < 2; mi++) {
        int r0 = row0 + wm + mi * 16 + gq;
        #pragma unroll
        for (int nj = 0; nj < 8; nj++) {
            int cb = wn + nj * 8 + 2 * tq;
            if (r0 < N_NODES)
                *(float2*)&g_tmp[(size_t)r0 * HIDDEN + cb] = make_float2(c[mi][nj][0], c[mi][nj][1]);
            if (r0 + 8 < N_NODES)
                *(float2*)&g_tmp[(size_t)(r0 + 8) * HIDDEN + cb] = make_float2(c[mi][nj][2], c[mi][nj][3]);
        }
    }
}

// ---------------- bias + LN + ReLU + residual: hnext = LN(g_tmp+b)*g+b relu + hcur ----------------
__global__ void ln_kernel(const float* __restrict__ conv_b, const float* __restrict__ ln_g,
                          const float* __restrict__ ln_b, int l, int cur) {
    int tid = threadIdx.x;
    int wid = tid >> 5;
    int lane = tid & 31;
    int row = blockIdx.x * 8 + wid;
    if (row >= N_NODES) return;
    int n0 = lane * 4;
    const float* hcur = g_h[cur];
    float* hnext = g_h[cur ^ 1];

    float4 v = *(const float4*)&g_tmp[(size_t)row * HIDDEN + n0];
    float4 cb = *(const float4*)&conv_b[l * HIDDEN + n0];
    v.x += cb.x; v.y += cb.y; v.z += cb.z; v.w += cb.w;
    float s = v.x + v.y + v.z + v.w;
    float q = v.x * v.x + v.y * v.y + v.z * v.z + v.w * v.w;
    #pragma unroll
    for (int o = 16; o > 0; o >>= 1) {
        s += __shfl_xor_sync(0xFFFFFFFFu, s, o);
        q += __shfl_xor_sync(0xFFFFFFFFu, q, o);
    }
    float mu = s * (1.0f / HIDDEN);
    float var = q * (1.0f / HIDDEN) - mu * mu;
    float rs = rsqrtf(var + LN_EPS);
    float4 g4 = *(const float4*)&ln_g[l * HIDDEN + n0];
    float4 b4 = *(const float4*)&ln_b[l * HIDDEN + n0];
    float4 rv = *(const float4*)&hcur[(size_t)row * HIDDEN + n0];
    float4 o;
    o.x = fmaxf((v.x - mu) * rs * g4.x + b4.x, 0.f) + rv.x;
    o.y = fmaxf((v.y - mu) * rs * g4.y + b4.y, 0.f) + rv.y;
    o.z = fmaxf((v.z - mu) * rs * g4.z + b4.z, 0.f) + rv.z;
    o.w = fmaxf((v.w - mu) * rs * g4.w + b4.w, 0.f) + rv.w;
    *(float4*)&hnext[(size_t)row * HIDDEN + n0] = o;
}

// ---------------- pooling ----------------
__device__ __forceinline__ int lower_bound_dev(const int* __restrict__ a, int n, int v) {
    int lo = 0, hi = n;
    while (lo < hi) { int mid = (lo + hi) >> 1; if (a[mid] < v) lo = mid + 1; else hi = mid; }
    return lo;
}

__global__ void pool_kernel(const int* __restrict__ batch, float* __restrict__ out, int finalbuf) {
    int g = blockIdx.x;
    int tid = threadIdx.x;
    int start = lower_bound_dev(batch, N_NODES, g);
    int end   = lower_bound_dev(batch, N_NODES, g + 1);
    const float* h = g_h[finalbuf];
    float acc = 0.f;
    for (int i = start; i < end; i++)
        acc += h[(size_t)i * HIDDEN + tid];
    out[g * HIDDEN + tid] = acc;
}

// ---------------- launch ----------------
extern "C" void kernel_launch(void* const* d_in, const int* in_sizes, int n_in,
                              void* d_out, int out_size) {
    const float* x      = (const float*)d_in[0];
    const int* ei       = (const int*)d_in[1];
    const int* et       = (const int*)d_in[2];
    const int* batch    = (const int*)d_in[3];
    const float* Wp     = (const float*)d_in[4];
    const float* bp     = (const float*)d_in[5];
    const float* rel_w  = (const float*)d_in[6];
    const float* root_w = (const float*)d_in[7];
    const float* conv_b = (const float*)d_in[8];
    const float* ln_g   = (const float*)d_in[9];
    const float* ln_b   = (const float*)d_in[10];
    float* out = (float*)d_out;

    zero_cnt_kernel<<<(N_NODES * N_REL + 255) / 256, 256>>>();
    count_kernel<<<(N_EDGES + 255) / 256, 256>>>(ei, et);
    proj_kernel<<<(N_NODES + BM - 1) / BM, 256>>>(x, Wp, bp);

    for (int l = 0; l < N_LAYERS; l++) {
        int cur = l & 1;
        zeroA_kernel<<<((N_NODES * (size_t)RK / 4) + 255) / 256, 256>>>();
        scatter_kernel<<<(N_EDGES + 7) / 8, 256>>>(ei, et, cur);
        bw_kernel<<<(KTOT * HIDDEN + 255) / 256, 256>>>(rel_w, root_w, l);
        gemm_mma_kernel<<<(N_NODES + 127) / 128, 256>>>(cur);
        ln_kernel<<<(N_NODES + 7) / 8, 256>>>(conv_b, ln_g, ln_b, l, cur);
    }

    pool_kernel<<<N_GRAPHS, HIDDEN>>>(batch, out, 0);
}

// round 7
// speedup vs baseline: 2.4988x; 1.4966x over previous
#include <cuda_runtime.h>
#include <cstdint>

#define N_NODES 50000
#define N_EDGES 600000
#define IN_DIM  64
#define HIDDEN  128
#define N_REL   10
#define N_LAYERS 6
#define N_GRAPHS 64
#define LN_EPS  1e-5f

#define KN      (HIDDEN + N_REL * HIDDEN)   // 1408: Y columns = [root | rel0..rel9]

// ---------------- device scratch ----------------
__device__ float g_Y[(size_t)N_NODES * KN];        // transformed features, 281.6 MB
__device__ float g_h[2][(size_t)N_NODES * HIDDEN]; // ping-pong features
__device__ float g_Bw[(size_t)N_LAYERS * HIDDEN * KN]; // packed tf32 weights [l][k][n]
__device__ int   g_cnt[N_NODES * N_REL];           // per-(dst,rel) in-degree
__device__ int   g_cntd[N_NODES];                  // per-dst in-degree
__device__ int   g_start[N_NODES];                 // CSR offsets
__device__ int   g_fill[N_NODES];                  // CSR fill cursors
__device__ int   g_coff[N_EDGES];                  // per-edge src column offset into Y
__device__ float g_cw[N_EDGES];                    // per-edge weight 1/cnt(dst,rel)

__device__ __forceinline__ float f2tf32(float f) {
    uint32_t r;
    asm("cvt.rna.tf32.f32 %0, %1;" : "=r"(r) : "f"(f));
    return __uint_as_float(r);
}

__device__ __forceinline__ void mma_tf32(float* c, const uint32_t* a, const uint32_t* b) {
    asm volatile(
        "mma.sync.aligned.m16n8k8.row.col.f32.tf32.tf32.f32 "
        "{%0,%1,%2,%3}, {%4,%5,%6,%7}, {%8,%9}, {%0,%1,%2,%3};"
        : "+f"(c[0]), "+f"(c[1]), "+f"(c[2]), "+f"(c[3])
        : "r"(a[0]), "r"(a[1]), "r"(a[2]), "r"(a[3]), "r"(b[0]), "r"(b[1]));
}

// ---------------- setup kernels (once per call) ----------------
__global__ void zero_cnt_kernel() {
    int i = blockIdx.x * blockDim.x + threadIdx.x;
    if (i < N_NODES * N_REL) g_cnt[i] = 0;
    if (i < N_NODES) { g_cntd[i] = 0; g_fill[i] = 0; }
}

__global__ void count_kernel(const int* __restrict__ ei, const int* __restrict__ et) {
    int e = blockIdx.x * blockDim.x + threadIdx.x;
    if (e >= N_EDGES) return;
    int dst = ei[N_EDGES + e];
    atomicAdd(&g_cnt[dst * N_REL + et[e]], 1);
    atomicAdd(&g_cntd[dst], 1);
}

// single-block exclusive scan of g_cntd -> g_start
__global__ void scan_kernel() {
    __shared__ int part[1024];
    int t = threadIdx.x;
    const int CH = (N_NODES + 1023) / 1024;   // 49
    int base = t * CH;
    int s = 0;
    for (int i = 0; i < CH; i++) {
        int idx = base + i;
        if (idx < N_NODES) s += g_cntd[idx];
    }
    part[t] = s;
    __syncthreads();
    for (int off = 1; off < 1024; off <<= 1) {
        int v = (t >= off) ? part[t - off] : 0;
        __syncthreads();
        part[t] += v;
        __syncthreads();
    }
    int run = (t > 0) ? part[t - 1] : 0;
    for (int i = 0; i < CH; i++) {
        int idx = base + i;
        if (idx < N_NODES) { g_start[idx] = run; run += g_cntd[idx]; }
    }
}

__global__ void fill_kernel(const int* __restrict__ ei, const int* __restrict__ et) {
    int e = blockIdx.x * blockDim.x + threadIdx.x;
    if (e >= N_EDGES) return;
    int src = ei[e];
    int dst = ei[N_EDGES + e];
    int r   = et[e];
    int pos = g_start[dst] + atomicAdd(&g_fill[dst], 1);
    g_coff[pos] = src * KN + HIDDEN + r * HIDDEN;
    g_cw[pos]   = 1.0f / (float)g_cnt[dst * N_REL + r];
}

// pack all layers' weights: g_Bw[l][k][n], n<128 -> root, else rel r=(n-128)/128
__global__ void bw_kernel(const float* __restrict__ rel_w, const float* __restrict__ root_w) {
    size_t idx = (size_t)blockIdx.x * blockDim.x + threadIdx.x;
    if (idx >= (size_t)N_LAYERS * HIDDEN * KN) return;
    int l = idx / (HIDDEN * KN);
    int rem = idx % (HIDDEN * KN);
    int k = rem / KN, n = rem % KN;
    float v;
    if (n < HIDDEN)
        v = root_w[(size_t)l * HIDDEN * HIDDEN + (size_t)k * HIDDEN + n];
    else {
        int r = (n - HIDDEN) / HIDDEN, j = (n - HIDDEN) % HIDDEN;
        v = rel_w[(size_t)l * N_REL * HIDDEN * HIDDEN + (size_t)r * HIDDEN * HIDDEN
                  + (size_t)k * HIDDEN + j];
    }
    g_Bw[idx] = f2tf32(v);
}

// ---------------- input projection ----------------
#define BM 64
#define BK 16
__global__ void proj_kernel(const float* __restrict__ x, const float* __restrict__ Wp,
                            const float* __restrict__ bp) {
    __shared__ float As[BK][BM + 4];
    __shared__ float Bs[BK][HIDDEN];
    int tid = threadIdx.x;
    int tm = tid >> 5, tn = tid & 31;
    int row0 = blockIdx.x * BM;
    float acc[8][4];
    #pragma unroll
    for (int i = 0; i < 8; i++)
        #pragma unroll
        for (int j = 0; j < 4; j++) acc[i][j] = 0.f;

    for (int k0 = 0; k0 < IN_DIM; k0 += BK) {
        {
            int r = tid >> 2, kc = (tid & 3) * 4, grow = row0 + r;
            float4 v = make_float4(0.f, 0.f, 0.f, 0.f);
            if (grow < N_NODES) v = *(const float4*)&x[(size_t)grow * IN_DIM + k0 + kc];
            As[kc + 0][r] = v.x; As[kc + 1][r] = v.y; As[kc + 2][r] = v.z; As[kc + 3][r] = v.w;
        }
        #pragma unroll
        for (int i = 0; i < 2; i++) {
            int f = tid + i * 256;
            int kk = f >> 5, c4 = (f & 31) * 4;
            *(float4*)&Bs[kk][c4] = *(const float4*)&Wp[(size_t)(k0 + kk) * HIDDEN + c4];
        }
        __syncthreads();
        #pragma unroll
        for (int kk = 0; kk < BK; kk++) {
            float a[8], b[4];
            *(float4*)&a[0] = *(const float4*)&As[kk][tm * 8];
            *(float4*)&a[4] = *(const float4*)&As[kk][tm * 8 + 4];
            *(float4*)&b[0] = *(const float4*)&Bs[kk][tn * 4];
            #pragma unroll
            for (int i = 0; i < 8; i++)
                #pragma unroll
                for (int j = 0; j < 4; j++) acc[i][j] = fmaf(a[i], b[j], acc[i][j]);
        }
        __syncthreads();
    }
    int n0 = tn * 4;
    float4 bb = *(const float4*)&bp[n0];
    #pragma unroll
    for (int i = 0; i < 8; i++) {
        int grow = row0 + tm * 8 + i;
        if (grow < N_NODES) {
            float4 o = make_float4(acc[i][0] + bb.x, acc[i][1] + bb.y,
                                   acc[i][2] + bb.z, acc[i][3] + bb.w);
            *(float4*)&g_h[0][(size_t)grow * HIDDEN + n0] = o;
        }
    }
}

// ---------------- tf32 GEMM: g_Y = h @ W_all   (M=50000, K=128, N=1408) ----------------
// grid: x = 11 N-blocks (fast-varying -> A reuse in L2), y = 391 M-blocks
#define APITCH 36
#define BPITCH 136

__global__ void __launch_bounds__(256, 2)
gemm_mma_kernel(int cur, int l) {
    __shared__ float As[128 * APITCH];
    __shared__ float Bs[32 * BPITCH];

    int tid = threadIdx.x;
    int wid = tid >> 5;
    int lane = tid & 31;
    int gq = lane >> 2;
    int tq = lane & 3;
    int wm = (wid >> 1) * 32;
    int wn = (wid & 1) * 64;
    int row0 = blockIdx.y * 128;
    int ncol0 = blockIdx.x * 128;
    const float* hcur = g_h[cur];
    const float* Bw = g_Bw + (size_t)l * HIDDEN * KN;

    float c[2][8][4];
    #pragma unroll
    for (int mi = 0; mi < 2; mi++)
        #pragma unroll
        for (int nj = 0; nj < 8; nj++)
            #pragma unroll
            for (int q = 0; q < 4; q++) c[mi][nj][q] = 0.f;

    const uint32_t* AsU = (const uint32_t*)As;
    const uint32_t* BsU = (const uint32_t*)Bs;

    #pragma unroll
    for (int i = 0; i < 4; i++) {
        int k0 = i * 32;
        float4 av[4], bv[4];
        #pragma unroll
        for (int t = 0; t < 4; t++) {
            int idx = tid + t * 256;            // 0..1023
            int r = idx >> 3, cc = idx & 7;
            int grow = row0 + r;
            av[t] = (grow < N_NODES)
                  ? *(const float4*)&hcur[(size_t)grow * HIDDEN + k0 + cc * 4]
                  : make_float4(0.f, 0.f, 0.f, 0.f);
        }
        #pragma unroll
        for (int t = 0; t < 4; t++) {
            int idx = tid + t * 256;            // 32x32 float4s
            int kk = idx >> 5, n4 = idx & 31;
            bv[t] = *(const float4*)&Bw[(size_t)(k0 + kk) * KN + ncol0 + n4 * 4];
        }
        __syncthreads();
        #pragma unroll
        for (int t = 0; t < 4; t++) {
            int idx = tid + t * 256;
            int r = idx >> 3, cc = idx & 7;
            float4 cv = make_float4(f2tf32(av[t].x), f2tf32(av[t].y),
                                    f2tf32(av[t].z), f2tf32(av[t].w));
            *(float4*)&As[r * APITCH + cc * 4] = cv;
        }
        #pragma unroll
        for (int t = 0; t < 4; t++) {
            int idx = tid + t * 256;
            int kk = idx >> 5, n4 = idx & 31;
            *(float4*)&Bs[kk * BPITCH + n4 * 4] = bv[t];
        }
        __syncthreads();

        #pragma unroll
        for (int s = 0; s < 4; s++) {
            int kb = s * 8;
            uint32_t a[2][4], b[8][2];
            #pragma unroll
            for (int mi = 0; mi < 2; mi++) {
                int r = wm + mi * 16 + gq;
                a[mi][0] = AsU[r * APITCH + kb + tq];
                a[mi][1] = AsU[(r + 8) * APITCH + kb + tq];
                a[mi][2] = AsU[r * APITCH + kb + tq + 4];
                a[mi][3] = AsU[(r + 8) * APITCH + kb + tq + 4];
            }
            #pragma unroll
            for (int nj = 0; nj < 8; nj++) {
                int n = wn + nj * 8 + gq;
                b[nj][0] = BsU[(kb + tq) * BPITCH + n];
                b[nj][1] = BsU[(kb + tq + 4) * BPITCH + n];
            }
            #pragma unroll
            for (int mi = 0; mi < 2; mi++)
                #pragma unroll
                for (int nj = 0; nj < 8; nj++)
                    mma_tf32(c[mi][nj], a[mi], b[nj]);
        }
        __syncthreads();
    }

    #pragma unroll
    for (int mi = 0; mi < 2; mi++) {
        int r0 = row0 + wm + mi * 16 + gq;
        #pragma unroll
        for (int nj = 0; nj < 8; nj++) {
            int cb = ncol0 + wn + nj * 8 + 2 * tq;
            if (r0 < N_NODES)
                *(float2*)&g_Y[(size_t)r0 * KN + cb] = make_float2(c[mi][nj][0], c[mi][nj][1]);
            if (r0 + 8 < N_NODES)
                *(float2*)&g_Y[(size_t)(r0 + 8) * KN + cb] = make_float2(c[mi][nj][2], c[mi][nj][3]);
        }
    }
}

// ---------------- fused CSR gather + bias + LN + ReLU + residual ----------------
// warp per dst node: acc = Y[dst, 0:128] + conv_b + sum_e w_e * Y[coff_e : +128]
__global__ void gather_ln_kernel(const float* __restrict__ conv_b, const float* __restrict__ ln_g,
                                 const float* __restrict__ ln_b, int l, int cur) {
    int wid = threadIdx.x >> 5;
    int lane = threadIdx.x & 31;
    int row = blockIdx.x * 8 + wid;
    if (row >= N_NODES) return;
    int n0 = lane * 4;
    const float* hcur = g_h[cur];
    float* hnext = g_h[cur ^ 1];

    float4 acc = *(const float4*)&g_Y[(size_t)row * KN + n0];
    float4 cb = *(const float4*)&conv_b[l * HIDDEN + n0];
    acc.x += cb.x; acc.y += cb.y; acc.z += cb.z; acc.w += cb.w;

    int s = g_start[row];
    int e = s + g_cntd[row];
    for (int i = s; i < e; i++) {
        int off = g_coff[i];
        float w = g_cw[i];
        float4 v = *(const float4*)&g_Y[(size_t)off + n0];
        acc.x = fmaf(v.x, w, acc.x);
        acc.y = fmaf(v.y, w, acc.y);
        acc.z = fmaf(v.z, w, acc.z);
        acc.w = fmaf(v.w, w, acc.w);
    }

    float sm = acc.x + acc.y + acc.z + acc.w;
    float q = acc.x * acc.x + acc.y * acc.y + acc.z * acc.z + acc.w * acc.w;
    #pragma unroll
    for (int o = 16; o > 0; o >>= 1) {
        sm += __shfl_xor_sync(0xFFFFFFFFu, sm, o);
        q  += __shfl_xor_sync(0xFFFFFFFFu, q, o);
    }
    float mu = sm * (1.0f / HIDDEN);
    float var = q * (1.0f / HIDDEN) - mu * mu;
    float rs = rsqrtf(var + LN_EPS);
    float4 g4 = *(const float4*)&ln_g[l * HIDDEN + n0];
    float4 b4 = *(const float4*)&ln_b[l * HIDDEN + n0];
    float4 rv = *(const float4*)&hcur[(size_t)row * HIDDEN + n0];
    float4 o;
    o.x = fmaxf((acc.x - mu) * rs * g4.x + b4.x, 0.f) + rv.x;
    o.y = fmaxf((acc.y - mu) * rs * g4.y + b4.y, 0.f) + rv.y;
    o.z = fmaxf((acc.z - mu) * rs * g4.z + b4.z, 0.f) + rv.z;
    o.w = fmaxf((acc.w - mu) * rs * g4.w + b4.w, 0.f) + rv.w;
    *(float4*)&hnext[(size_t)row * HIDDEN + n0] = o;
}

// ---------------- pooling ----------------
__device__ __forceinline__ int lower_bound_dev(const int* __restrict__ a, int n, int v) {
    int lo = 0, hi = n;
    while (lo < hi) { int mid = (lo + hi) >> 1; if (a[mid] < v) lo = mid + 1; else hi = mid; }
    return lo;
}

__global__ void pool_kernel(const int* __restrict__ batch, float* __restrict__ out, int finalbuf) {
    int g = blockIdx.x;
    int tid = threadIdx.x;
    int start = lower_bound_dev(batch, N_NODES, g);
    int end   = lower_bound_dev(batch, N_NODES, g + 1);
    const float* h = g_h[finalbuf];
    float acc = 0.f;
    for (int i = start; i < end; i++)
        acc += h[(size_t)i * HIDDEN + tid];
    out[g * HIDDEN + tid] = acc;
}

// ---------------- launch ----------------
extern "C" void kernel_launch(void* const* d_in, const int* in_sizes, int n_in,
                              void* d_out, int out_size) {
    const float* x      = (const float*)d_in[0];
    const int* ei       = (const int*)d_in[1];
    const int* et       = (const int*)d_in[2];
    const int* batch    = (const int*)d_in[3];
    const float* Wp     = (const float*)d_in[4];
    const float* bp     = (const float*)d_in[5];
    const float* rel_w  = (const float*)d_in[6];
    const float* root_w = (const float*)d_in[7];
    const float* conv_b = (const float*)d_in[8];
    const float* ln_g   = (const float*)d_in[9];
    const float* ln_b   = (const float*)d_in[10];
    float* out = (float*)d_out;

    // CSR + counts (structure only)
    zero_cnt_kernel<<<(N_NODES * N_REL + 255) / 256, 256>>>();
    count_kernel<<<(N_EDGES + 255) / 256, 256>>>(ei, et);
    scan_kernel<<<1, 1024>>>();
    fill_kernel<<<(N_EDGES + 255) / 256, 256>>>(ei, et);

    // weights packed once for all layers
    bw_kernel<<<(int)(((size_t)N_LAYERS * HIDDEN * KN + 255) / 256), 256>>>(rel_w, root_w);

    proj_kernel<<<(N_NODES + BM - 1) / BM, 256>>>(x, Wp, bp);

    dim3 ggrid(KN / 128, (N_NODES + 127) / 128);
    for (int l = 0; l < N_LAYERS; l++) {
        int cur = l & 1;
        gemm_mma_kernel<<<ggrid, 256>>>(cur, l);
        gather_ln_kernel<<<(N_NODES + 7) / 8, 256>>>(conv_b, ln_g, ln_b, l, cur);
    }

    pool_kernel<<<N_GRAPHS, HIDDEN>>>(batch, out, 0);
}